// round 9
// baseline (speedup 1.0000x reference)
#include <cuda_runtime.h>
#include <cuda_bf16.h>
#include <cstdint>

// Problem constants
#define NE 400000
#define NN 50000
#define H  128
#define FN 64
#define FE 16
#define KEI 80
#define KFN 192
#define AS_STRIDE 129

// Scratch
__device__ float g_hA[(size_t)NE * H];
__device__ float g_hB[(size_t)NE * H];
__device__ float g_agg[4][(size_t)NN * H];
// Conv W pre-split bf16, transposed [n][k]
__device__ __nv_bfloat16 g_Whi[3][H * H];
__device__ __nv_bfloat16 g_Wlo[3][H * H];
// Edge-init W pre-split bf16, transposed [n][k], k padded 80->88
__device__ __nv_bfloat16 g_EWhi[H * 88];
__device__ __nv_bfloat16 g_EWlo[H * 88];

// ---------------------------------------------------------------------------
// PTX helpers (sm_80+ baseline only; tcgen05 rejected by compute_103 target)
// ---------------------------------------------------------------------------
__device__ __forceinline__ uint32_t smem_u32(const void* p) {
    uint32_t a;
    asm("{ .reg .u64 t; cvta.to.shared.u64 t, %1; cvt.u32.u64 %0, t; }" : "=r"(a) : "l"(p));
    return a;
}
__device__ __forceinline__ void red_add_v4(float* p, float4 v) {
    asm volatile("red.global.add.v4.f32 [%0], {%1, %2, %3, %4};"
                 :: "l"(p), "f"(v.x), "f"(v.y), "f"(v.z), "f"(v.w) : "memory");
}
__device__ __forceinline__ void ldsm_x4(uint32_t* r, uint32_t addr) {
    asm volatile("ldmatrix.sync.aligned.m8n8.x4.shared.b16 {%0,%1,%2,%3}, [%4];"
                 : "=r"(r[0]), "=r"(r[1]), "=r"(r[2]), "=r"(r[3]) : "r"(addr));
}
__device__ __forceinline__ void mma_bf16(float* d, const uint32_t* a, const uint32_t* b) {
    asm volatile("mma.sync.aligned.m16n8k16.row.col.f32.bf16.bf16.f32 "
                 "{%0,%1,%2,%3}, {%4,%5,%6,%7}, {%8,%9}, {%0,%1,%2,%3};"
                 : "+f"(d[0]), "+f"(d[1]), "+f"(d[2]), "+f"(d[3])
                 : "r"(a[0]), "r"(a[1]), "r"(a[2]), "r"(a[3]), "r"(b[0]), "r"(b[1]));
}
__device__ __forceinline__ uint32_t pack_split(float v0, float v1, uint32_t& lo) {
    __nv_bfloat16 h0 = __float2bfloat16(v0), h1 = __float2bfloat16(v1);
    __nv_bfloat16 l0 = __float2bfloat16(v0 - __bfloat162float(h0));
    __nv_bfloat16 l1 = __float2bfloat16(v1 - __bfloat162float(h1));
    lo = (uint32_t)__bfloat16_as_ushort(l0) | ((uint32_t)__bfloat16_as_ushort(l1) << 16);
    return (uint32_t)__bfloat16_as_ushort(h0) | ((uint32_t)__bfloat16_as_ushort(h1) << 16);
}

// ---------------------------------------------------------------------------
__global__ void k_zero() {
    size_t n4 = ((size_t)4 * NN * H) / 4;
    float4* p = (float4*)g_agg;
    for (size_t i = (size_t)blockIdx.x * blockDim.x + threadIdx.x; i < n4;
         i += (size_t)gridDim.x * blockDim.x)
        p[i] = make_float4(0.f, 0.f, 0.f, 0.f);
}

// Pre-split conv W (3*H*H) and edge-init W (KEI*H)
__global__ void k_prep_w(const float* __restrict__ Wc, const float* __restrict__ We0) {
    int idx = blockIdx.x * blockDim.x + threadIdx.x;
    if (idx < 3 * H * H) {
        int d = idx / (H * H), r = idx % (H * H);
        int k = r / H, n = r % H;
        float w = Wc[idx];
        __nv_bfloat16 hi = __float2bfloat16(w);
        __nv_bfloat16 lo = __float2bfloat16(w - __bfloat162float(hi));
        g_Whi[d][n * H + k] = hi;
        g_Wlo[d][n * H + k] = lo;
    } else if (idx < 3 * H * H + KEI * H) {
        int r = idx - 3 * H * H;
        int k = r / H, n = r % H;
        float w = We0[r];
        __nv_bfloat16 hi = __float2bfloat16(w);
        __nv_bfloat16 lo = __float2bfloat16(w - __bfloat162float(hi));
        g_EWhi[n * 88 + k] = hi;
        g_EWlo[n * 88 + k] = lo;
    }
}

// ---------------------------------------------------------------------------
// Shared warp-level MMA core: per-warp 32 rows x 32 cols, split-bf16 3-pass.
// ---------------------------------------------------------------------------
template <int KS, int ROWB>
__device__ __forceinline__ void mma_tile(uint32_t sb, uint32_t aHi, uint32_t aLo,
                                         uint32_t bHi, uint32_t bLo,
                                         int wm, int wn, int lane,
                                         float acc[2][4][4]) {
    uint32_t aRow = (uint32_t)(wm * 32 + (lane & 15)) * ROWB + (uint32_t)(lane >> 4) * 16;
    uint32_t bRow = (uint32_t)(wn * 32 + (lane & 7) + ((lane >> 4) & 1) * 8) * ROWB
                  + (uint32_t)((lane >> 3) & 1) * 16;
#pragma unroll
    for (int kk = 0; kk < KS; kk++) {
        uint32_t koff = 32u * kk;
        uint32_t ah[2][4], al[2][4];
        ldsm_x4(ah[0], sb + aHi + aRow + koff);
        ldsm_x4(ah[1], sb + aHi + aRow + 16 * ROWB + koff);
        ldsm_x4(al[0], sb + aLo + aRow + koff);
        ldsm_x4(al[1], sb + aLo + aRow + 16 * ROWB + koff);
#pragma unroll
        for (int ntp = 0; ntp < 2; ntp++) {
            uint32_t bh[4], bl[4];
            ldsm_x4(bh, sb + bHi + bRow + ntp * (16 * ROWB) + koff);
            ldsm_x4(bl, sb + bLo + bRow + ntp * (16 * ROWB) + koff);
#pragma unroll
            for (int mt = 0; mt < 2; mt++) {
                mma_bf16(acc[mt][2 * ntp],     ah[mt], bh);
                mma_bf16(acc[mt][2 * ntp],     ah[mt], bl);
                mma_bf16(acc[mt][2 * ntp],     al[mt], bh);
                mma_bf16(acc[mt][2 * ntp + 1], ah[mt], bh + 2);
                mma_bf16(acc[mt][2 * ntp + 1], ah[mt], bl + 2);
                mma_bf16(acc[mt][2 * ntp + 1], al[mt], bh + 2);
            }
        }
    }
}

// Write C fragments to smem (stride 132 floats at byte offset coff)
__device__ __forceinline__ void store_c(char* smem, int coff, int wm, int wn,
                                        int lane, float acc[2][4][4]) {
    float* Cf = (float*)(smem + coff);
#pragma unroll
    for (int mt = 0; mt < 2; mt++)
#pragma unroll
        for (int j = 0; j < 4; j++)
#pragma unroll
            for (int half = 0; half < 2; half++) {
                int row = wm * 32 + mt * 16 + (lane >> 2) + half * 8;
                int col = wn * 32 + j * 8 + (lane & 3) * 2;
                *(float2*)(Cf + row * 132 + col) =
                    make_float2(acc[mt][j][2 * half], acc[mt][j][2 * half + 1]);
            }
}

// ---------------------------------------------------------------------------
// Conv layer: 128 edges/block, 512 threads, HMMA + smem-C v4 epilogue
// ---------------------------------------------------------------------------
#define CVROW 272
#define CV_BS   0
#define CV_SCOL 512
#define CV_AHI  1024
#define CV_ALO  (CV_AHI + 128 * CVROW)
#define CV_BHI  (CV_ALO + 128 * CVROW)
#define CV_BLO  (CV_BHI + 128 * CVROW)
#define CV_SMEM (CV_BLO + 128 * CVROW)   // 140288

__global__ void __launch_bounds__(512) k_conv(
    int sel, int d, const int* __restrict__ ei, const float* __restrict__ bias)
{
    extern __shared__ __align__(1024) char smem[];
    uint32_t sb = smem_u32(smem);
    float* bs = (float*)(smem + CV_BS);
    int* s_col = (int*)(smem + CV_SCOL);

    const float* hIn  = sel ? g_hB : g_hA;
    float*       hOut = sel ? g_hA : g_hB;
    const float* aggIn  = g_agg[d];
    float*       aggOut = g_agg[d + 1];

    int tid = threadIdx.x, wid = tid >> 5, lane = tid & 31;
    int e0 = blockIdx.x * 128;

    // W hi/lo -> smem (row pad 128 -> 136 bf16)
    {
        const uint32_t* whi = (const uint32_t*)g_Whi[d];
        const uint32_t* wlo = (const uint32_t*)g_Wlo[d];
        uint32_t* shi = (uint32_t*)(smem + CV_BHI);
        uint32_t* slo = (uint32_t*)(smem + CV_BLO);
        for (int i = tid; i < 128 * 64; i += 512) {
            int row = i >> 6, c = i & 63;
            shi[row * 68 + c] = whi[i];
            slo[row * 68 + c] = wlo[i];
        }
    }
    if (tid < H) bs[tid] = bias[tid];
    if (tid < 128) s_col[tid] = ei[NE + e0 + tid];

    // Stage A = agg[row] - h[e^1] (each warp 8 rows)
    int rr[8];
#pragma unroll
    for (int t = 0; t < 8; t++) rr[t] = ei[e0 + wid * 8 + t];
#pragma unroll
    for (int t = 0; t < 8; t++) {
        int m = wid * 8 + t;
        int e = e0 + m;
        const float* ap = aggIn + (size_t)rr[t] * H;
        const float* hp = hIn + (size_t)(e ^ 1) * H;
#pragma unroll
        for (int q = 0; q < 2; q++) {
            int cc = 2 * lane + 64 * q;
            float2 av = *(const float2*)(ap + cc);
            float2 hv = *(const float2*)(hp + cc);
            uint32_t lw, hw = pack_split(av.x - hv.x, av.y - hv.y, lw);
            uint32_t boff = (uint32_t)m * CVROW + (uint32_t)cc * 2;
            *(uint32_t*)(smem + CV_AHI + boff) = hw;
            *(uint32_t*)(smem + CV_ALO + boff) = lw;
        }
    }
    __syncthreads();

    int wm = wid & 3, wn = wid >> 2;
    float acc[2][4][4] = {};
    mma_tile<8, CVROW>(sb, CV_AHI, CV_ALO, CV_BHI, CV_BLO, wm, wn, lane, acc);

    __syncthreads();                 // A dead; reuse as C
    store_c(smem, CV_AHI, wm, wn, lane, acc);
    __syncthreads();

    // v4 epilogue: thread -> row tid>>2, cols (tid&3)*4 + 16g
    {
        const float* Cf = (const float*)(smem + CV_AHI);
        int r = tid >> 2;
        int e = e0 + r;
        float* hrow = hOut + (size_t)e * H;
        float* arow = aggOut + (size_t)s_col[r] * H;
        int cb = (tid & 3) * 4;
#pragma unroll
        for (int g = 0; g < 8; g++) {
            int col = cb + 16 * g;
            float4 v = *(const float4*)(Cf + r * 132 + col);
            float4 b = *(const float4*)(bs + col);
            float4 o;
            o.x = fmaxf(v.x + b.x, 0.f);
            o.y = fmaxf(v.y + b.y, 0.f);
            o.z = fmaxf(v.z + b.z, 0.f);
            o.w = fmaxf(v.w + b.w, 0.f);
            *(float4*)(hrow + col) = o;
            red_add_v4(arow + col, o);
        }
    }
}

// ---------------------------------------------------------------------------
// Edge init: h0 = relu([x[row]; ea] @ W + b), HMMA K=80 (5 k-steps)
// ---------------------------------------------------------------------------
#define EROW 176
#define E_BS   0
#define E_SCOL 512
#define E_AHI  1024
#define E_ALO  (E_AHI + 128 * EROW)    // 23552
#define E_WHI  (E_ALO + 128 * EROW)    // 46080
#define E_WLO  (E_WHI + 128 * EROW)    // 68608
#define E_SMEM (E_WLO + 128 * EROW)    // 91136

__global__ void __launch_bounds__(512) k_edge_init(
    const float* __restrict__ x, const float* __restrict__ ea,
    const int* __restrict__ ei, const float* __restrict__ bias)
{
    extern __shared__ __align__(1024) char smem[];
    uint32_t sb = smem_u32(smem);
    float* bs = (float*)(smem + E_BS);
    int* s_col = (int*)(smem + E_SCOL);

    int tid = threadIdx.x, wid = tid >> 5, lane = tid & 31;
    int e0 = blockIdx.x * 128;

    // W images are pre-padded to 88 bf16/row == EROW bytes: linear copy
    {
        const float4* whi = (const float4*)g_EWhi;
        const float4* wlo = (const float4*)g_EWlo;
        float4* shi = (float4*)(smem + E_WHI);
        float4* slo = (float4*)(smem + E_WLO);
        for (int i = tid; i < (128 * EROW) / 16; i += 512) {
            shi[i] = whi[i];
            slo[i] = wlo[i];
        }
    }
    if (tid < H) bs[tid] = bias[tid];
    if (tid < 128) s_col[tid] = ei[NE + e0 + tid];

    // Stage A: cols 0..63 = x[row], 64..79 = edge_attr
    int rr[8];
#pragma unroll
    for (int t = 0; t < 8; t++) rr[t] = ei[e0 + wid * 8 + t];
#pragma unroll
    for (int t = 0; t < 8; t++) {
        int m = wid * 8 + t;
        int e = e0 + m;
        const float* xp = x + (size_t)rr[t] * FN;
        float2 xv = *(const float2*)(xp + 2 * lane);
        uint32_t lw, hw = pack_split(xv.x, xv.y, lw);
        uint32_t boff = (uint32_t)m * EROW + (uint32_t)lane * 4;
        *(uint32_t*)(smem + E_AHI + boff) = hw;
        *(uint32_t*)(smem + E_ALO + boff) = lw;
        if (lane < 8) {
            float2 ev = *(const float2*)(ea + (size_t)e * FE + 2 * lane);
            uint32_t lw2, hw2 = pack_split(ev.x, ev.y, lw2);
            uint32_t bo2 = (uint32_t)m * EROW + 128 + (uint32_t)lane * 4;
            *(uint32_t*)(smem + E_AHI + bo2) = hw2;
            *(uint32_t*)(smem + E_ALO + bo2) = lw2;
        }
    }
    __syncthreads();

    int wm = wid & 3, wn = wid >> 2;
    float acc[2][4][4] = {};
    mma_tile<5, EROW>(sb, E_AHI, E_ALO, E_WHI, E_WLO, wm, wn, lane, acc);

    __syncthreads();                 // A + W dead; reuse as C
    store_c(smem, E_AHI, wm, wn, lane, acc);
    __syncthreads();

    {
        const float* Cf = (const float*)(smem + E_AHI);
        int r = tid >> 2;
        int e = e0 + r;
        float* hrow = g_hA + (size_t)e * H;
        float* arow = g_agg[0] + (size_t)s_col[r] * H;
        int cb = (tid & 3) * 4;
#pragma unroll
        for (int g = 0; g < 8; g++) {
            int col = cb + 16 * g;
            float4 v = *(const float4*)(Cf + r * 132 + col);
            float4 b = *(const float4*)(bs + col);
            float4 o;
            o.x = fmaxf(v.x + b.x, 0.f);
            o.y = fmaxf(v.y + b.y, 0.f);
            o.z = fmaxf(v.z + b.z, 0.f);
            o.w = fmaxf(v.w + b.w, 0.f);
            *(float4*)(hrow + col) = o;
            red_add_v4(arow + col, o);
        }
    }
}

// ---------------------------------------------------------------------------
// fp32 GEMM for k_final (unchanged, passing since R3)
// ---------------------------------------------------------------------------
template <int K>
__device__ __forceinline__ void gemm_tile(const float* __restrict__ As,
                                          const float* __restrict__ Ws,
                                          float c[8][8], int tx, int ty) {
    float a[8], b[8], an[8], bn[8];
    {
        const float* Ap = As + ty * 8;
#pragma unroll
        for (int i = 0; i < 8; i++) a[i] = Ap[i];
        float4 q0 = *(const float4*)(Ws + tx * 8);
        float4 q1 = *(const float4*)(Ws + tx * 8 + 4);
        b[0]=q0.x; b[1]=q0.y; b[2]=q0.z; b[3]=q0.w;
        b[4]=q1.x; b[5]=q1.y; b[6]=q1.z; b[7]=q1.w;
    }
#pragma unroll 4
    for (int k = 0; k < K; k++) {
        if (k + 1 < K) {
            const float* Ap = As + (k + 1) * AS_STRIDE + ty * 8;
#pragma unroll
            for (int i = 0; i < 8; i++) an[i] = Ap[i];
            float4 q0 = *(const float4*)(Ws + (k + 1) * H + tx * 8);
            float4 q1 = *(const float4*)(Ws + (k + 1) * H + tx * 8 + 4);
            bn[0]=q0.x; bn[1]=q0.y; bn[2]=q0.z; bn[3]=q0.w;
            bn[4]=q1.x; bn[5]=q1.y; bn[6]=q1.z; bn[7]=q1.w;
        }
#pragma unroll
        for (int i = 0; i < 8; i++)
#pragma unroll
            for (int j = 0; j < 8; j++)
                c[i][j] = fmaf(a[i], b[j], c[i][j]);
#pragma unroll
        for (int i = 0; i < 8; i++) { a[i] = an[i]; b[i] = bn[i]; }
    }
}

__global__ void __launch_bounds__(256) k_final(
    const float* __restrict__ x, const float* __restrict__ W,
    const float* __restrict__ bias, float* __restrict__ out)
{
    const float* s = g_agg[3];
    extern __shared__ __align__(1024) float sm[];
    float* As = sm;
    float* Ws = As + KFN * AS_STRIDE;
    float* bs = Ws + KFN * H;

    int tid = threadIdx.x;
    int n0 = blockIdx.x * 128;
    int warp = tid >> 5, lane = tid & 31;

    for (int i = tid; i < (KFN * H) / 4; i += 256)
        ((float4*)Ws)[i] = ((const float4*)W)[i];
    if (tid < H) bs[tid] = bias[tid];

#pragma unroll
    for (int t = 0; t < 16; t++) {
        int m = warp * 16 + t;
        int node = n0 + m;
        int nc = node < NN ? node : NN - 1;
        const float* xp = x + (size_t)nc * FN;
        As[lane * AS_STRIDE + m]        = xp[lane];
        As[(lane + 32) * AS_STRIDE + m] = xp[lane + 32];
        const float* sp = s + (size_t)nc * H;
#pragma unroll
        for (int q = 0; q < 4; q++) {
            int k = FN + lane + 32 * q;
            As[k * AS_STRIDE + m] = sp[lane + 32 * q];
        }
    }
    __syncthreads();

    int tx = tid & 15, ty = tid >> 4;
    float c[8][8] = {};
    gemm_tile<KFN>(As, Ws, c, tx, ty);

#pragma unroll
    for (int i = 0; i < 8; i++) {
        int m = ty * 8 + i;
        int node = n0 + m;
        if (node >= NN) continue;
        float4 o0, o1;
        o0.x = fmaxf(c[i][0] + bs[tx * 8 + 0], 0.f);
        o0.y = fmaxf(c[i][1] + bs[tx * 8 + 1], 0.f);
        o0.z = fmaxf(c[i][2] + bs[tx * 8 + 2], 0.f);
        o0.w = fmaxf(c[i][3] + bs[tx * 8 + 3], 0.f);
        o1.x = fmaxf(c[i][4] + bs[tx * 8 + 4], 0.f);
        o1.y = fmaxf(c[i][5] + bs[tx * 8 + 5], 0.f);
        o1.z = fmaxf(c[i][6] + bs[tx * 8 + 6], 0.f);
        o1.w = fmaxf(c[i][7] + bs[tx * 8 + 7], 0.f);
        float* op = out + (size_t)node * H + tx * 8;
        *(float4*)op = o0;
        *(float4*)(op + 4) = o1;
    }
}

// ---------------------------------------------------------------------------
// Launch
// ---------------------------------------------------------------------------
extern "C" void kernel_launch(void* const* d_in, const int* in_sizes, int n_in,
                              void* d_out, int out_size) {
    const float* x  = (const float*)d_in[0];
    const float* ea = (const float*)d_in[1];
    const int*   ei = (const int*)d_in[2];
    const float* W0 = (const float*)d_in[3];
    const float* b0 = (const float*)d_in[4];
    const float* Wc = (const float*)d_in[5];
    const float* bc = (const float*)d_in[6];
    const float* We = (const float*)d_in[7];
    const float* be = (const float*)d_in[8];
    float* out = (float*)d_out;

    const int smem_fn = (KFN * AS_STRIDE + KFN * H + H) * 4;

    cudaFuncSetAttribute(k_edge_init, cudaFuncAttributeMaxDynamicSharedMemorySize, E_SMEM);
    cudaFuncSetAttribute(k_conv,      cudaFuncAttributeMaxDynamicSharedMemorySize, CV_SMEM);
    cudaFuncSetAttribute(k_final,     cudaFuncAttributeMaxDynamicSharedMemorySize, smem_fn);

    k_zero<<<2048, 256>>>();
    k_prep_w<<<(3 * H * H + KEI * H + 255) / 256, 256>>>(Wc, W0);
    k_edge_init<<<NE / 128, 512, E_SMEM>>>(x, ea, ei, b0);
    for (int d = 0; d < 3; d++)
        k_conv<<<NE / 128, 512, CV_SMEM>>>(d & 1, d, ei, bc + (size_t)d * H);
    k_final<<<(NN + 127) / 128, 256, smem_fn>>>(x, We, be, out);
}